// round 3
// baseline (speedup 1.0000x reference)
#include <cuda_runtime.h>
#include <cstdint>

typedef unsigned long long ull;

#define LOCN   40001
#define BATCH  1024
#define TSTEPS 256

#define ROWS_PER_CTA 7
#define NCTA ((BATCH + ROWS_PER_CTA - 1) / ROWS_PER_CTA)   // 147
#define HSTRIDE 112      // padded h row length (floats); lane ko covers k in [14ko,14ko+14)
#define KPT 14
#define NPAIR 7
#define SCR_BYTES (ROWS_PER_CTA * 500 * 4)   // 14000, multiple of 16

// ---------------- device scratch ----------------
__device__ float g_Gloc[(size_t)LOCN * 600];
__device__ float g_Pt[92 * 100];
__device__ float g_Ps[92 * 100];
__device__ float g_scr[(size_t)TSTEPS * BATCH * 500 + 4096];

// ---------------- helpers ----------------
__device__ __forceinline__ float sigf(float x) { return 1.f / (1.f + __expf(-x)); }
__device__ __forceinline__ float tanh_fast(float x) { return 1.f - 2.f / (1.f + __expf(2.f * x)); }

__device__ __forceinline__ ull pack2(float lo, float hi) {
    ull r; asm("mov.b64 %0, {%1, %2};" : "=l"(r) : "f"(lo), "f"(hi)); return r;
}
__device__ __forceinline__ void unpack2(ull v, float& lo, float& hi) {
    asm("mov.b64 {%0, %1}, %2;" : "=f"(lo), "=f"(hi) : "l"(v));
}
__device__ __forceinline__ void fma2(ull& acc, ull a, ull b) {
    asm("fma.rn.f32x2 %0, %1, %2, %0;" : "+l"(acc) : "l"(a), "l"(b));
}
__device__ __forceinline__ uint32_t smem_u32(const void* p) {
    uint32_t a;
    asm("{ .reg .u64 t; cvta.to.shared.u64 t, %1; cvt.u32.u64 %0, t; }" : "=r"(a) : "l"(p));
    return a;
}
__device__ __forceinline__ void mbar_init(uint32_t mbar, uint32_t cnt) {
    asm volatile("mbarrier.init.shared.b64 [%0], %1;" :: "r"(mbar), "r"(cnt) : "memory");
}
__device__ __forceinline__ void mbar_expect_tx(uint32_t mbar, uint32_t bytes) {
    asm volatile("mbarrier.arrive.expect_tx.shared.b64 _, [%0], %1;" :: "r"(mbar), "r"(bytes) : "memory");
}
__device__ __forceinline__ void bulk_g2s(uint32_t dst, const void* src, uint32_t bytes, uint32_t mbar) {
    asm volatile("cp.async.bulk.shared::cta.global.mbarrier::complete_tx::bytes [%0], [%1], %2, [%3];"
                 :: "r"(dst), "l"(src), "r"(bytes), "r"(mbar) : "memory");
}
__device__ __forceinline__ void mbar_wait(uint32_t mbar, uint32_t parity) {
    uint32_t done;
    asm volatile("{\n\t.reg .pred p;\n\t"
                 "mbarrier.try_wait.parity.acquire.cta.shared::cta.b64 p, [%1], %2;\n\t"
                 "selp.b32 %0, 1, 0, p;\n\t}"
                 : "=r"(done) : "r"(mbar), "r"(parity) : "memory");
    if (!done) {
        asm volatile("{\n\t.reg .pred P1;\n\t"
                     "WL_%=:\n\t"
                     "mbarrier.try_wait.parity.acquire.cta.shared::cta.b64 P1, [%0], %1, 0x989680;\n\t"
                     "@P1 bra.uni WD_%=;\n\t"
                     "bra.uni WL_%=;\n\t"
                     "WD_%=:\n\t}"
                     :: "r"(mbar), "r"(parity) : "memory");
    }
}

// =======================================================================
// Kernel A: Gloc = emb_loc @ [W_ih|W_xt|W_xs] + biases
// =======================================================================
__global__ void kernA(const float* __restrict__ emb_loc,
                      const float* __restrict__ W_ih,
                      const float* __restrict__ W_xt,
                      const float* __restrict__ W_xs,
                      const float* __restrict__ b,
                      const float* __restrict__ b_t,
                      const float* __restrict__ b_s)
{
    __shared__ __align__(16) float As[50 * 64];
    __shared__ __align__(16) float Bs[50 * 64];

    const int tid = threadIdx.x;
    const int m0 = blockIdx.x * 64;
    const int n0 = blockIdx.y * 64;
    const int tx = tid & 15, ty = tid >> 4;
    const int r0 = ty * 4, c0 = tx * 4;

    ull acc[4][2];
#pragma unroll
    for (int i = 0; i < 4; i++) { acc[i][0] = 0ull; acc[i][1] = 0ull; }

    for (int kp = 0; kp < 100; kp += 50) {
        for (int i = tid; i < 64 * 50; i += 256) {
            int r = i / 50, k = i % 50;
            int row = m0 + r;
            As[k * 64 + r] = (row < LOCN) ? emb_loc[(size_t)row * 100 + kp + k] : 0.f;
        }
        for (int i = tid; i < 64 * 50; i += 256) {
            int k = i / 64, c = i % 64;
            int col = n0 + c, kk = kp + k;
            float v = 0.f;
            if (col < 400)      v = W_ih[kk * 400 + col];
            else if (col < 500) v = W_xt[kk * 100 + (col - 400)];
            else if (col < 600) v = W_xs[kk * 100 + (col - 500)];
            Bs[k * 64 + c] = v;
        }
        __syncthreads();

#pragma unroll 5
        for (int k = 0; k < 50; k++) {
            float4 a4 = *(const float4*)(As + k * 64 + r0);
            ulonglong2 bv = *(const ulonglong2*)(Bs + k * 64 + c0);
            ull a0 = pack2(a4.x, a4.x);
            ull a1 = pack2(a4.y, a4.y);
            ull a2 = pack2(a4.z, a4.z);
            ull a3 = pack2(a4.w, a4.w);
            fma2(acc[0][0], a0, bv.x); fma2(acc[0][1], a0, bv.y);
            fma2(acc[1][0], a1, bv.x); fma2(acc[1][1], a1, bv.y);
            fma2(acc[2][0], a2, bv.x); fma2(acc[2][1], a2, bv.y);
            fma2(acc[3][0], a3, bv.x); fma2(acc[3][1], a3, bv.y);
        }
        __syncthreads();
    }

    float bias[4];
#pragma unroll
    for (int p = 0; p < 4; p++) {
        int col = n0 + c0 + p;
        float bv = 0.f;
        if (col < 400)      bv = b[col];
        else if (col < 500) bv = b_t[col - 400];
        else if (col < 600) bv = b_s[col - 500];
        bias[p] = bv;
    }
#pragma unroll
    for (int r = 0; r < 4; r++) {
        int row = m0 + r0 + r;
        if (row >= LOCN) continue;
        float v0, v1, v2, v3;
        unpack2(acc[r][0], v0, v1);
        unpack2(acc[r][1], v2, v3);
        float v[4] = { v0 + bias[0], v1 + bias[1], v2 + bias[2], v3 + bias[3] };
#pragma unroll
        for (int p = 0; p < 4; p++) {
            int col = n0 + c0 + p;
            if (col < 600) g_Gloc[(size_t)row * 600 + col] = v[p];
        }
    }
}

// =======================================================================
// Kernel B: P_t = emb_t @ W_tt ; P_s = emb_s @ W_ss
// =======================================================================
__global__ void kernB(const float* __restrict__ emb_t, const float* __restrict__ W_tt,
                      const float* __restrict__ emb_s, const float* __restrict__ W_ss)
{
    int i = blockIdx.x * blockDim.x + threadIdx.x;
    if (i >= 92 * 100 * 2) return;
    int which = i / 9200;
    int r = i % 9200;
    int s = r / 100, j = r % 100;
    const float* e = which ? emb_s : emb_t;
    const float* W = which ? W_ss : W_tt;
    float acc = 0.f;
#pragma unroll
    for (int d = 0; d < 12; d++) acc += e[s * 12 + d] * W[d * 100 + j];
    (which ? g_Ps : g_Pt)[s * 100 + j] = acc;
}

// =======================================================================
// Kernel C: gather + tsg -> scratch [t][b][ pre(400) | tsg(100) ]
// =======================================================================
__global__ void kernC(const int* __restrict__ traj,
                      const int* __restrict__ tu, const int* __restrict__ tl,
                      const int* __restrict__ tu_slot, const int* __restrict__ tl_slot,
                      const int* __restrict__ su, const int* __restrict__ sl,
                      const int* __restrict__ su_slot, const int* __restrict__ sl_slot)
{
    const int w = threadIdx.x >> 5, lane = threadIdx.x & 31;
    const int token = blockIdx.x * 8 + w;
    const int bb = token >> 8, t = token & 255;

    const int idx = traj[token];
    const float ut = (float)tu_slot[token], lt = (float)tl_slot[token];
    const float us = (float)su_slot[token], ls = (float)sl_slot[token];
    const float rdt = 1.f / fmaxf(ut + lt, 1.f);
    const float rds = 1.f / fmaxf(us + ls, 1.f);
    const float* Ptl = g_Pt + tl[token] * 100;
    const float* Ptu = g_Pt + tu[token] * 100;
    const float* Psl = g_Ps + sl[token] * 100;
    const float* Psu = g_Ps + su[token] * 100;

    const float* g = g_Gloc + (size_t)idx * 600;
    float* o = g_scr + ((size_t)t * BATCH + bb) * 500;

    const float4* g4 = (const float4*)g;
    float4* o4 = (float4*)o;
    for (int q = lane; q < 100; q += 32) o4[q] = g4[q];

    for (int j = lane; j < 100; j += 32) {
        float pt = g[400 + j] + (ut * Ptl[j] + lt * Ptu[j]) * rdt;
        float ps = g[500 + j] + (us * Psl[j] + ls * Psu[j]) * rds;
        o[400 + j] = sigf(pt) * sigf(ps);
    }
}

// =======================================================================
// Kernel D v3: 147 CTAs x 7 rows, 800 threads (25 warps).
//   tid = j*8 + ko ;  j in [0,100), ko in [0,8)
//   lane ko covers k in [14ko, 14ko+14) of the (zero-padded to 112) h vector.
//   weights in regs as (k,k+1) pairs per gate; fma.rn.f32x2 mainloop.
//   Reduce-scatter over 8 lanes (4 shfls) -> gate g fully summed on lanes
//   {2g, 2g+1}; activations computed in parallel per lane; 3 shfl.idx gather
//   to lane 0 which updates c (smem) and writes h.
//   Scratch double-buffered 2 steps ahead via cp.async.bulk.
// =======================================================================
__global__ void __launch_bounds__(800, 1)
kernD(const float* __restrict__ W_hh, float* __restrict__ out)
{
    __shared__ __align__(16) float hbuf[2][ROWS_PER_CTA][HSTRIDE];
    __shared__ __align__(16) float sscr[2][ROWS_PER_CTA * 500];
    __shared__ __align__(16) float cbuf[ROWS_PER_CTA][100];
    __shared__ __align__(8)  ull  smbar[2];

    const int tid = threadIdx.x;
    const int j = tid >> 3, ko = tid & 7;
    const int gate = ko >> 1;               // 0:i 1:f 2:g 3:o
    const int row0 = blockIdx.x * ROWS_PER_CTA;

    // ---- weights into registers: (k,k+1) pairs for this lane's gate? No —
    // each lane needs all 4 gates for its k-slice (reduction is over k). ----
    ull wi[NPAIR], wf[NPAIR], wg[NPAIR], wo[NPAIR];
#pragma unroll
    for (int m = 0; m < NPAIR; m++) {
        int k0 = ko * KPT + 2 * m, k1 = k0 + 1;
        float i0 = 0.f, i1 = 0.f, f0 = 0.f, f1 = 0.f;
        float g0 = 0.f, g1 = 0.f, o0 = 0.f, o1 = 0.f;
        if (k0 < 100) {
            const float* wr = W_hh + k0 * 400;
            i0 = wr[j]; f0 = wr[100 + j]; g0 = wr[200 + j]; o0 = wr[300 + j];
        }
        if (k1 < 100) {
            const float* wr = W_hh + k1 * 400;
            i1 = wr[j]; f1 = wr[100 + j]; g1 = wr[200 + j]; o1 = wr[300 + j];
        }
        wi[m] = pack2(i0, i1);
        wf[m] = pack2(f0, f1);
        wg[m] = pack2(g0, g1);
        wo[m] = pack2(o0, o1);
    }

    // ---- init smem ----
    {
        float* p = &hbuf[0][0][0];
        for (int i = tid; i < 2 * ROWS_PER_CTA * HSTRIDE; i += 800) p[i] = 0.f;
        float* pc = &cbuf[0][0];
        for (int i = tid; i < ROWS_PER_CTA * 100; i += 800) pc[i] = 0.f;
    }
    uint32_t mb0 = smem_u32(&smbar[0]);
    uint32_t mb1 = smem_u32(&smbar[1]);
    uint32_t sc0 = smem_u32(&sscr[0][0]);
    uint32_t sc1 = smem_u32(&sscr[1][0]);
    if (tid == 0) { mbar_init(mb0, 1); mbar_init(mb1, 1); }
    __syncthreads();

    const float* scr_base = g_scr + (size_t)row0 * 500;
    if (tid == 0) {
        mbar_expect_tx(mb0, SCR_BYTES);
        bulk_g2s(sc0, scr_base, SCR_BYTES, mb0);
        mbar_expect_tx(mb1, SCR_BYTES);
        bulk_g2s(sc1, scr_base + (size_t)BATCH * 500, SCR_BYTES, mb1);
    }

#pragma unroll 1
    for (int t = 0; t < TSTEPS; t++) {
        const int buf = t & 1;
        mbar_wait(buf ? mb1 : mb0, (t >> 1) & 1);

        const float* sb = sscr[buf];
        const float* hc = &hbuf[buf][0][0];
        float* hn = &hbuf[buf ^ 1][0][0];

#pragma unroll
        for (int r = 0; r < ROWS_PER_CTA; r++) {
            // per-lane preact for its gate (broadcast-friendly LDS)
            const float* pr = sb + r * 500;
            float p = pr[gate * 100 + j];
            float tsg = (gate == 2) ? pr[400 + j] : 0.f;

            // mainloop: 7 pairs x 4 gates of fp32x2 FMA
            const ull* h2 = (const ull*)(hc + r * HSTRIDE + ko * KPT);
            ull ai2 = 0ull, af2 = 0ull, ag2 = 0ull, ao2 = 0ull;
#pragma unroll
            for (int m = 0; m < NPAIR; m++) {
                ull h = h2[m];
                fma2(ai2, h, wi[m]);
                fma2(af2, h, wf[m]);
                fma2(ag2, h, wg[m]);
                fma2(ao2, h, wo[m]);
            }
            float si, sf, sg, so, xl, xh;
            unpack2(ai2, xl, xh); si = xl + xh;
            unpack2(af2, xl, xh); sf = xl + xh;
            unpack2(ag2, xl, xh); sg = xl + xh;
            unpack2(ao2, xl, xh); so = xl + xh;

            // reduce-scatter across 8 ko lanes (4 shfls)
            float s1 = (ko & 4) ? si : sg;
            float s2 = (ko & 4) ? sf : so;
            float r1 = __shfl_xor_sync(0xffffffffu, s1, 4, 8);
            float r2 = __shfl_xor_sync(0xffffffffu, s2, 4, 8);
            float x0, x1;
            if (ko & 4) { x0 = sg + r1; x1 = so + r2; }
            else        { x0 = si + r1; x1 = sf + r2; }

            float s3 = (ko & 2) ? x0 : x1;
            float r3 = __shfl_xor_sync(0xffffffffu, s3, 2, 8);
            float x = (ko & 2) ? (x1 + r3) : (x0 + r3);

            x += __shfl_xor_sync(0xffffffffu, x, 1, 8);
            // now: lanes 0,1 -> i ; 2,3 -> f ; 4,5 -> g ; 6,7 -> o (full sums)

            // parallel activations
            float v = x + p;
            float act;
            if (gate == 2) act = tanh_fast(v) * tsg;   // gg * tsg
            else           act = sigf(v);

            // gather to lane 0 of each 8-group
            float vf = __shfl_sync(0xffffffffu, act, 2, 8);
            float vg = __shfl_sync(0xffffffffu, act, 4, 8);
            float vo = __shfl_sync(0xffffffffu, act, 6, 8);

            if (ko == 0) {
                float cOld = cbuf[r][j];
                float cN = vf * cOld + act * vg;       // act = gi
                cbuf[r][j] = cN;
                float h = vo * tanh_fast(cN);
                hn[r * HSTRIDE + j] = h;
                if (t == TSTEPS - 1 && row0 + r < BATCH) out[(row0 + r) * 100 + j] = h;
            }
        }
        __syncthreads();

        if (t + 2 < TSTEPS && tid == 0) {
            uint32_t mb = buf ? mb1 : mb0;
            mbar_expect_tx(mb, SCR_BYTES);
            bulk_g2s(buf ? sc1 : sc0, scr_base + (size_t)(t + 2) * BATCH * 500, SCR_BYTES, mb);
        }
    }
}

// =======================================================================
// launch
// =======================================================================
extern "C" void kernel_launch(void* const* d_in, const int* in_sizes, int n_in,
                              void* d_out, int out_size)
{
    (void)in_sizes; (void)n_in; (void)out_size;
    const int*   traj    = (const int*)d_in[0];
    const int*   tu      = (const int*)d_in[3];
    const int*   tl      = (const int*)d_in[4];
    const int*   tu_s    = (const int*)d_in[5];
    const int*   tl_s    = (const int*)d_in[6];
    const int*   su      = (const int*)d_in[7];
    const int*   sl      = (const int*)d_in[8];
    const int*   su_s    = (const int*)d_in[9];
    const int*   sl_s    = (const int*)d_in[10];
    const float* emb_loc = (const float*)d_in[11];
    const float* emb_t   = (const float*)d_in[12];
    const float* emb_s   = (const float*)d_in[13];
    const float* W_ih    = (const float*)d_in[14];
    const float* W_hh    = (const float*)d_in[15];
    const float* b       = (const float*)d_in[16];
    const float* W_xt    = (const float*)d_in[17];
    const float* W_tt    = (const float*)d_in[18];
    const float* b_t     = (const float*)d_in[19];
    const float* W_xs    = (const float*)d_in[20];
    const float* W_ss    = (const float*)d_in[21];
    const float* b_s     = (const float*)d_in[22];
    float* out = (float*)d_out;

    dim3 gA((LOCN + 63) / 64, 10);
    kernA<<<gA, 256>>>(emb_loc, W_ih, W_xt, W_xs, b, b_t, b_s);

    kernB<<<(92 * 100 * 2 + 255) / 256, 256>>>(emb_t, W_tt, emb_s, W_ss);

    kernC<<<(BATCH * TSTEPS) / 8, 256>>>(traj, tu, tl, tu_s, tl_s, su, sl, su_s, sl_s);

    kernD<<<NCTA, 800>>>(W_hh, out);
}

// round 4
// speedup vs baseline: 1.2158x; 1.2158x over previous
#include <cuda_runtime.h>
#include <cstdint>

typedef unsigned long long ull;

#define LOCN   40001
#define BATCH  1024
#define TSTEPS 256

#define ROWS_PER_CTA 7
#define NCTA ((BATCH + ROWS_PER_CTA - 1) / ROWS_PER_CTA)   // 147
#define HS 100                                // h row length (400 B, 16B aligned)
#define SCR_BYTES (ROWS_PER_CTA * 500 * 4)    // 14000, multiple of 16

// ---------------- device scratch ----------------
__device__ float g_Gloc[(size_t)LOCN * 600];
__device__ float g_Pt[92 * 100];
__device__ float g_Ps[92 * 100];
__device__ float g_scr[(size_t)TSTEPS * BATCH * 500 + 4096];

// ---------------- helpers ----------------
__device__ __forceinline__ float sigf(float x) { return 1.f / (1.f + __expf(-x)); }
__device__ __forceinline__ float tanh_fast(float x) { return 1.f - 2.f / (1.f + __expf(2.f * x)); }

__device__ __forceinline__ ull pack2(float lo, float hi) {
    ull r; asm("mov.b64 %0, {%1, %2};" : "=l"(r) : "f"(lo), "f"(hi)); return r;
}
__device__ __forceinline__ void unpack2(ull v, float& lo, float& hi) {
    asm("mov.b64 {%0, %1}, %2;" : "=f"(lo), "=f"(hi) : "l"(v));
}
__device__ __forceinline__ void fma2(ull& acc, ull a, ull b) {
    asm("fma.rn.f32x2 %0, %1, %2, %0;" : "+l"(acc) : "l"(a), "l"(b));
}
__device__ __forceinline__ uint32_t smem_u32(const void* p) {
    uint32_t a;
    asm("{ .reg .u64 t; cvta.to.shared.u64 t, %1; cvt.u32.u64 %0, t; }" : "=r"(a) : "l"(p));
    return a;
}
__device__ __forceinline__ void mbar_init(uint32_t mbar, uint32_t cnt) {
    asm volatile("mbarrier.init.shared.b64 [%0], %1;" :: "r"(mbar), "r"(cnt) : "memory");
}
__device__ __forceinline__ void mbar_expect_tx(uint32_t mbar, uint32_t bytes) {
    asm volatile("mbarrier.arrive.expect_tx.shared.b64 _, [%0], %1;" :: "r"(mbar), "r"(bytes) : "memory");
}
__device__ __forceinline__ void bulk_g2s(uint32_t dst, const void* src, uint32_t bytes, uint32_t mbar) {
    asm volatile("cp.async.bulk.shared::cta.global.mbarrier::complete_tx::bytes [%0], [%1], %2, [%3];"
                 :: "r"(dst), "l"(src), "r"(bytes), "r"(mbar) : "memory");
}
__device__ __forceinline__ void mbar_wait(uint32_t mbar, uint32_t parity) {
    uint32_t done;
    asm volatile("{\n\t.reg .pred p;\n\t"
                 "mbarrier.try_wait.parity.acquire.cta.shared::cta.b64 p, [%1], %2;\n\t"
                 "selp.b32 %0, 1, 0, p;\n\t}"
                 : "=r"(done) : "r"(mbar), "r"(parity) : "memory");
    if (!done) {
        asm volatile("{\n\t.reg .pred P1;\n\t"
                     "WL_%=:\n\t"
                     "mbarrier.try_wait.parity.acquire.cta.shared::cta.b64 P1, [%0], %1, 0x989680;\n\t"
                     "@P1 bra.uni WD_%=;\n\t"
                     "bra.uni WL_%=;\n\t"
                     "WD_%=:\n\t}"
                     :: "r"(mbar), "r"(parity) : "memory");
    }
}

// =======================================================================
// Kernel A: Gloc = emb_loc @ [W_ih|W_xt|W_xs] + biases
// =======================================================================
__global__ void kernA(const float* __restrict__ emb_loc,
                      const float* __restrict__ W_ih,
                      const float* __restrict__ W_xt,
                      const float* __restrict__ W_xs,
                      const float* __restrict__ b,
                      const float* __restrict__ b_t,
                      const float* __restrict__ b_s)
{
    __shared__ __align__(16) float As[50 * 64];
    __shared__ __align__(16) float Bs[50 * 64];

    const int tid = threadIdx.x;
    const int m0 = blockIdx.x * 64;
    const int n0 = blockIdx.y * 64;
    const int tx = tid & 15, ty = tid >> 4;
    const int r0 = ty * 4, c0 = tx * 4;

    ull acc[4][2];
#pragma unroll
    for (int i = 0; i < 4; i++) { acc[i][0] = 0ull; acc[i][1] = 0ull; }

    for (int kp = 0; kp < 100; kp += 50) {
        for (int i = tid; i < 64 * 50; i += 256) {
            int r = i / 50, k = i % 50;
            int row = m0 + r;
            As[k * 64 + r] = (row < LOCN) ? emb_loc[(size_t)row * 100 + kp + k] : 0.f;
        }
        for (int i = tid; i < 64 * 50; i += 256) {
            int k = i / 64, c = i % 64;
            int col = n0 + c, kk = kp + k;
            float v = 0.f;
            if (col < 400)      v = W_ih[kk * 400 + col];
            else if (col < 500) v = W_xt[kk * 100 + (col - 400)];
            else if (col < 600) v = W_xs[kk * 100 + (col - 500)];
            Bs[k * 64 + c] = v;
        }
        __syncthreads();

#pragma unroll 5
        for (int k = 0; k < 50; k++) {
            float4 a4 = *(const float4*)(As + k * 64 + r0);
            ulonglong2 bv = *(const ulonglong2*)(Bs + k * 64 + c0);
            ull a0 = pack2(a4.x, a4.x);
            ull a1 = pack2(a4.y, a4.y);
            ull a2 = pack2(a4.z, a4.z);
            ull a3 = pack2(a4.w, a4.w);
            fma2(acc[0][0], a0, bv.x); fma2(acc[0][1], a0, bv.y);
            fma2(acc[1][0], a1, bv.x); fma2(acc[1][1], a1, bv.y);
            fma2(acc[2][0], a2, bv.x); fma2(acc[2][1], a2, bv.y);
            fma2(acc[3][0], a3, bv.x); fma2(acc[3][1], a3, bv.y);
        }
        __syncthreads();
    }

    float bias[4];
#pragma unroll
    for (int p = 0; p < 4; p++) {
        int col = n0 + c0 + p;
        float bv = 0.f;
        if (col < 400)      bv = b[col];
        else if (col < 500) bv = b_t[col - 400];
        else if (col < 600) bv = b_s[col - 500];
        bias[p] = bv;
    }
#pragma unroll
    for (int r = 0; r < 4; r++) {
        int row = m0 + r0 + r;
        if (row >= LOCN) continue;
        float v0, v1, v2, v3;
        unpack2(acc[r][0], v0, v1);
        unpack2(acc[r][1], v2, v3);
        float v[4] = { v0 + bias[0], v1 + bias[1], v2 + bias[2], v3 + bias[3] };
#pragma unroll
        for (int p = 0; p < 4; p++) {
            int col = n0 + c0 + p;
            if (col < 600) g_Gloc[(size_t)row * 600 + col] = v[p];
        }
    }
}

// =======================================================================
// Kernel B: P_t = emb_t @ W_tt ; P_s = emb_s @ W_ss
// =======================================================================
__global__ void kernB(const float* __restrict__ emb_t, const float* __restrict__ W_tt,
                      const float* __restrict__ emb_s, const float* __restrict__ W_ss)
{
    int i = blockIdx.x * blockDim.x + threadIdx.x;
    if (i >= 92 * 100 * 2) return;
    int which = i / 9200;
    int r = i % 9200;
    int s = r / 100, j = r % 100;
    const float* e = which ? emb_s : emb_t;
    const float* W = which ? W_ss : W_tt;
    float acc = 0.f;
#pragma unroll
    for (int d = 0; d < 12; d++) acc += e[s * 12 + d] * W[d * 100 + j];
    (which ? g_Ps : g_Pt)[s * 100 + j] = acc;
}

// =======================================================================
// Kernel C: gather + tsg -> scratch [t][b][ pre(400) | tsg(100) ]
// =======================================================================
__global__ void kernC(const int* __restrict__ traj,
                      const int* __restrict__ tu, const int* __restrict__ tl,
                      const int* __restrict__ tu_slot, const int* __restrict__ tl_slot,
                      const int* __restrict__ su, const int* __restrict__ sl,
                      const int* __restrict__ su_slot, const int* __restrict__ sl_slot)
{
    const int w = threadIdx.x >> 5, lane = threadIdx.x & 31;
    const int token = blockIdx.x * 8 + w;
    const int bb = token >> 8, t = token & 255;

    const int idx = traj[token];
    const float ut = (float)tu_slot[token], lt = (float)tl_slot[token];
    const float us = (float)su_slot[token], ls = (float)sl_slot[token];
    const float rdt = 1.f / fmaxf(ut + lt, 1.f);
    const float rds = 1.f / fmaxf(us + ls, 1.f);
    const float* Ptl = g_Pt + tl[token] * 100;
    const float* Ptu = g_Pt + tu[token] * 100;
    const float* Psl = g_Ps + sl[token] * 100;
    const float* Psu = g_Ps + su[token] * 100;

    const float* g = g_Gloc + (size_t)idx * 600;
    float* o = g_scr + ((size_t)t * BATCH + bb) * 500;

    const float4* g4 = (const float4*)g;
    float4* o4 = (float4*)o;
    for (int q = lane; q < 100; q += 32) o4[q] = g4[q];

    for (int j = lane; j < 100; j += 32) {
        float pt = g[400 + j] + (ut * Ptl[j] + lt * Ptu[j]) * rdt;
        float ps = g[500 + j] + (us * Psl[j] + ls * Psu[j]) * rds;
        o[400 + j] = sigf(pt) * sigf(ps);
    }
}

// =======================================================================
// Kernel D v4: output-column ownership, NO cross-lane reduction.
//  416 threads: threads 0..399 own output column n (gate = n/100, j = n%100),
//  holding W_hh[:, n] as 50 packed f32x2 registers.
//  Phase 1 (per row r): h row (100 floats, contiguous) read via LDS.128
//    broadcast; 50 FFMA2; add preact; activation; STS act -> acts[r][n].
//  Phase 2: 700 (r,j) pairs over threads (c kept in registers):
//    cN = f*c + i*tsg*g ; h = o*tanh(cN) -> hbuf[next].
//  Scratch staged 2 steps ahead via cp.async.bulk (as before).
// =======================================================================
__global__ void __launch_bounds__(416, 1)
kernD(const float* __restrict__ W_hh, float* __restrict__ out)
{
    __shared__ __align__(16) float hbuf[2][ROWS_PER_CTA][HS];
    __shared__ __align__(16) float acts[ROWS_PER_CTA][400];
    __shared__ __align__(16) float sscr[2][ROWS_PER_CTA * 500];
    __shared__ __align__(8)  ull  smbar[2];

    const int tid = threadIdx.x;
    const int n = tid;                       // output column (valid if < 400)
    const bool p1act = (n < 400);
    const int gate = n / 100;                // 0:i 1:f 2:g 3:o (only if p1act)
    const int row0 = blockIdx.x * ROWS_PER_CTA;

    // phase-2 assignment: pairs tid and tid+416 (< 700)
    const int q0 = tid;                      // q0 < 700 always (416 <= 700)
    const int q1 = tid + 416;
    const int r_0 = q0 / 100, j_0 = q0 % 100;
    const int r_1 = (q1 < 700) ? q1 / 100 : 0, j_1 = (q1 < 700) ? q1 % 100 : 0;
    const bool has_q1 = (q1 < 700);

    // ---- weights into registers: w[m] covers k = {2m, 2m+1} for column n ----
    ull w[50];
#pragma unroll
    for (int m = 0; m < 50; m++) {
        float lo = 0.f, hi = 0.f;
        if (p1act) {
            lo = W_hh[(2 * m) * 400 + n];
            hi = W_hh[(2 * m + 1) * 400 + n];
        }
        w[m] = pack2(lo, hi);
    }

    // ---- init smem ----
    {
        float* p = &hbuf[0][0][0];
        for (int i = tid; i < 2 * ROWS_PER_CTA * HS; i += 416) p[i] = 0.f;
    }
    uint32_t mb0 = smem_u32(&smbar[0]);
    uint32_t mb1 = smem_u32(&smbar[1]);
    uint32_t sc0 = smem_u32(&sscr[0][0]);
    uint32_t sc1 = smem_u32(&sscr[1][0]);
    if (tid == 0) { mbar_init(mb0, 1); mbar_init(mb1, 1); }
    __syncthreads();

    const float* scr_base = g_scr + (size_t)row0 * 500;
    if (tid == 0) {
        mbar_expect_tx(mb0, SCR_BYTES);
        bulk_g2s(sc0, scr_base, SCR_BYTES, mb0);
        mbar_expect_tx(mb1, SCR_BYTES);
        bulk_g2s(sc1, scr_base + (size_t)BATCH * 500, SCR_BYTES, mb1);
    }

    float c0 = 0.f, c1 = 0.f;                // cell state for phase-2 pairs

#pragma unroll 1
    for (int t = 0; t < TSTEPS; t++) {
        const int buf = t & 1;
        mbar_wait(buf ? mb1 : mb0, (t >> 1) & 1);

        const float* sb = sscr[buf];
        const float* hc = &hbuf[buf][0][0];
        float* hn = &hbuf[buf ^ 1][0][0];

        // ---------------- phase 1: gate pre-sums + activations ----------------
        if (p1act) {
#pragma unroll
            for (int r = 0; r < ROWS_PER_CTA; r++) {
                const ulonglong2* h2 = (const ulonglong2*)(hc + r * HS);
                ull a0 = 0ull, a1 = 0ull, a2 = 0ull, a3 = 0ull;
#pragma unroll
                for (int m = 0; m < 12; m++) {
                    ulonglong2 hv = h2[2 * m];
                    fma2(a0, hv.x, w[4 * m + 0]);
                    fma2(a1, hv.y, w[4 * m + 1]);
                    ulonglong2 hw = h2[2 * m + 1];
                    fma2(a2, hw.x, w[4 * m + 2]);
                    fma2(a3, hw.y, w[4 * m + 3]);
                }
                {   // last pair m=24 (k=96..99)
                    ulonglong2 hv = h2[24];
                    fma2(a0, hv.x, w[48]);
                    fma2(a1, hv.y, w[49]);
                }
                float xl, xh, s0, s1, s2, s3;
                unpack2(a0, xl, xh); s0 = xl + xh;
                unpack2(a1, xl, xh); s1 = xl + xh;
                unpack2(a2, xl, xh); s2 = xl + xh;
                unpack2(a3, xl, xh); s3 = xl + xh;
                float v = (s0 + s1) + (s2 + s3) + sb[r * 500 + n];
                float act = (gate == 2) ? tanh_fast(v) : sigf(v);
                acts[r][n] = act;
            }
        }
        __syncthreads();

        // ---------------- phase 2: c/h update ----------------
        {
            const float* a0p = &acts[r_0][0];
            float gi = a0p[j_0], gf = a0p[100 + j_0], gg = a0p[200 + j_0], go = a0p[300 + j_0];
            float tsg = sb[r_0 * 500 + 400 + j_0];
            float cN = gf * c0 + gi * tsg * gg;
            c0 = cN;
            float h = go * tanh_fast(cN);
            hn[r_0 * HS + j_0] = h;
            if (t == TSTEPS - 1 && row0 + r_0 < BATCH) out[(row0 + r_0) * 100 + j_0] = h;
        }
        if (has_q1) {
            const float* a1p = &acts[r_1][0];
            float gi = a1p[j_1], gf = a1p[100 + j_1], gg = a1p[200 + j_1], go = a1p[300 + j_1];
            float tsg = sb[r_1 * 500 + 400 + j_1];
            float cN = gf * c1 + gi * tsg * gg;
            c1 = cN;
            float h = go * tanh_fast(cN);
            hn[r_1 * HS + j_1] = h;
            if (t == TSTEPS - 1 && row0 + r_1 < BATCH) out[(row0 + r_1) * 100 + j_1] = h;
        }
        __syncthreads();

        if (t + 2 < TSTEPS && tid == 0) {
            uint32_t mb = buf ? mb1 : mb0;
            mbar_expect_tx(mb, SCR_BYTES);
            bulk_g2s(buf ? sc1 : sc0, scr_base + (size_t)(t + 2) * BATCH * 500, SCR_BYTES, mb);
        }
    }
}

// =======================================================================
// launch
// =======================================================================
extern "C" void kernel_launch(void* const* d_in, const int* in_sizes, int n_in,
                              void* d_out, int out_size)
{
    (void)in_sizes; (void)n_in; (void)out_size;
    const int*   traj    = (const int*)d_in[0];
    const int*   tu      = (const int*)d_in[3];
    const int*   tl      = (const int*)d_in[4];
    const int*   tu_s    = (const int*)d_in[5];
    const int*   tl_s    = (const int*)d_in[6];
    const int*   su      = (const int*)d_in[7];
    const int*   sl      = (const int*)d_in[8];
    const int*   su_s    = (const int*)d_in[9];
    const int*   sl_s    = (const int*)d_in[10];
    const float* emb_loc = (const float*)d_in[11];
    const float* emb_t   = (const float*)d_in[12];
    const float* emb_s   = (const float*)d_in[13];
    const float* W_ih    = (const float*)d_in[14];
    const float* W_hh    = (const float*)d_in[15];
    const float* b       = (const float*)d_in[16];
    const float* W_xt    = (const float*)d_in[17];
    const float* W_tt    = (const float*)d_in[18];
    const float* b_t     = (const float*)d_in[19];
    const float* W_xs    = (const float*)d_in[20];
    const float* W_ss    = (const float*)d_in[21];
    const float* b_s     = (const float*)d_in[22];
    float* out = (float*)d_out;

    dim3 gA((LOCN + 63) / 64, 10);
    kernA<<<gA, 256>>>(emb_loc, W_ih, W_xt, W_xs, b, b_t, b_s);

    kernB<<<(92 * 100 * 2 + 255) / 256, 256>>>(emb_t, W_tt, emb_s, W_ss);

    kernC<<<(BATCH * TSTEPS) / 8, 256>>>(traj, tu, tl, tu_s, tl_s, su, sl, su_s, sl_s);

    kernD<<<NCTA, 416>>>(W_hh, out);
}

// round 5
// speedup vs baseline: 1.2373x; 1.0177x over previous
#include <cuda_runtime.h>
#include <cstdint>

typedef unsigned long long ull;

#define LOCN   40001
#define BATCH  1024
#define TSTEPS 256

#define ROWS_PER_CTA 7
#define NCTA ((BATCH + ROWS_PER_CTA - 1) / ROWS_PER_CTA)   // 147
#define HSTRIDE 104                          // padded: half0 at [0,52), half1 at [52,104)
#define SCR_BYTES (ROWS_PER_CTA * 500 * 4)   // 14000, multiple of 16

// ---------------- device scratch ----------------
__device__ float g_Gloc[(size_t)LOCN * 600];
__device__ float g_Pt[92 * 100];
__device__ float g_Ps[92 * 100];
__device__ float g_scr[(size_t)TSTEPS * BATCH * 500 + 4096];

// ---------------- helpers ----------------
__device__ __forceinline__ float sigf(float x) { return 1.f / (1.f + __expf(-x)); }
__device__ __forceinline__ float tanh_fast(float x) { return 1.f - 2.f / (1.f + __expf(2.f * x)); }

__device__ __forceinline__ ull pack2(float lo, float hi) {
    ull r; asm("mov.b64 %0, {%1, %2};" : "=l"(r) : "f"(lo), "f"(hi)); return r;
}
__device__ __forceinline__ void unpack2(ull v, float& lo, float& hi) {
    asm("mov.b64 {%0, %1}, %2;" : "=f"(lo), "=f"(hi) : "l"(v));
}
__device__ __forceinline__ void fma2(ull& acc, ull a, ull b) {
    asm("fma.rn.f32x2 %0, %1, %2, %0;" : "+l"(acc) : "l"(a), "l"(b));
}
__device__ __forceinline__ uint32_t smem_u32(const void* p) {
    uint32_t a;
    asm("{ .reg .u64 t; cvta.to.shared.u64 t, %1; cvt.u32.u64 %0, t; }" : "=r"(a) : "l"(p));
    return a;
}
__device__ __forceinline__ void mbar_init(uint32_t mbar, uint32_t cnt) {
    asm volatile("mbarrier.init.shared.b64 [%0], %1;" :: "r"(mbar), "r"(cnt) : "memory");
}
__device__ __forceinline__ void mbar_expect_tx(uint32_t mbar, uint32_t bytes) {
    asm volatile("mbarrier.arrive.expect_tx.shared.b64 _, [%0], %1;" :: "r"(mbar), "r"(bytes) : "memory");
}
__device__ __forceinline__ void bulk_g2s(uint32_t dst, const void* src, uint32_t bytes, uint32_t mbar) {
    asm volatile("cp.async.bulk.shared::cta.global.mbarrier::complete_tx::bytes [%0], [%1], %2, [%3];"
                 :: "r"(dst), "l"(src), "r"(bytes), "r"(mbar) : "memory");
}
__device__ __forceinline__ void mbar_wait(uint32_t mbar, uint32_t parity) {
    uint32_t done;
    asm volatile("{\n\t.reg .pred p;\n\t"
                 "mbarrier.try_wait.parity.acquire.cta.shared::cta.b64 p, [%1], %2;\n\t"
                 "selp.b32 %0, 1, 0, p;\n\t}"
                 : "=r"(done) : "r"(mbar), "r"(parity) : "memory");
    if (!done) {
        asm volatile("{\n\t.reg .pred P1;\n\t"
                     "WL_%=:\n\t"
                     "mbarrier.try_wait.parity.acquire.cta.shared::cta.b64 P1, [%0], %1, 0x989680;\n\t"
                     "@P1 bra.uni WD_%=;\n\t"
                     "bra.uni WL_%=;\n\t"
                     "WD_%=:\n\t}"
                     :: "r"(mbar), "r"(parity) : "memory");
    }
}

// =======================================================================
// Kernel A: Gloc = emb_loc @ [W_ih|W_xt|W_xs] + biases
// =======================================================================
__global__ void kernA(const float* __restrict__ emb_loc,
                      const float* __restrict__ W_ih,
                      const float* __restrict__ W_xt,
                      const float* __restrict__ W_xs,
                      const float* __restrict__ b,
                      const float* __restrict__ b_t,
                      const float* __restrict__ b_s)
{
    __shared__ __align__(16) float As[50 * 64];
    __shared__ __align__(16) float Bs[50 * 64];

    const int tid = threadIdx.x;
    const int m0 = blockIdx.x * 64;
    const int n0 = blockIdx.y * 64;
    const int tx = tid & 15, ty = tid >> 4;
    const int r0 = ty * 4, c0 = tx * 4;

    ull acc[4][2];
#pragma unroll
    for (int i = 0; i < 4; i++) { acc[i][0] = 0ull; acc[i][1] = 0ull; }

    for (int kp = 0; kp < 100; kp += 50) {
        for (int i = tid; i < 64 * 50; i += 256) {
            int r = i / 50, k = i % 50;
            int row = m0 + r;
            As[k * 64 + r] = (row < LOCN) ? emb_loc[(size_t)row * 100 + kp + k] : 0.f;
        }
        for (int i = tid; i < 64 * 50; i += 256) {
            int k = i / 64, c = i % 64;
            int col = n0 + c, kk = kp + k;
            float v = 0.f;
            if (col < 400)      v = W_ih[kk * 400 + col];
            else if (col < 500) v = W_xt[kk * 100 + (col - 400)];
            else if (col < 600) v = W_xs[kk * 100 + (col - 500)];
            Bs[k * 64 + c] = v;
        }
        __syncthreads();

#pragma unroll 5
        for (int k = 0; k < 50; k++) {
            float4 a4 = *(const float4*)(As + k * 64 + r0);
            ulonglong2 bv = *(const ulonglong2*)(Bs + k * 64 + c0);
            ull a0 = pack2(a4.x, a4.x);
            ull a1 = pack2(a4.y, a4.y);
            ull a2 = pack2(a4.z, a4.z);
            ull a3 = pack2(a4.w, a4.w);
            fma2(acc[0][0], a0, bv.x); fma2(acc[0][1], a0, bv.y);
            fma2(acc[1][0], a1, bv.x); fma2(acc[1][1], a1, bv.y);
            fma2(acc[2][0], a2, bv.x); fma2(acc[2][1], a2, bv.y);
            fma2(acc[3][0], a3, bv.x); fma2(acc[3][1], a3, bv.y);
        }
        __syncthreads();
    }

    float bias[4];
#pragma unroll
    for (int p = 0; p < 4; p++) {
        int col = n0 + c0 + p;
        float bv = 0.f;
        if (col < 400)      bv = b[col];
        else if (col < 500) bv = b_t[col - 400];
        else if (col < 600) bv = b_s[col - 500];
        bias[p] = bv;
    }
#pragma unroll
    for (int r = 0; r < 4; r++) {
        int row = m0 + r0 + r;
        if (row >= LOCN) continue;
        float v0, v1, v2, v3;
        unpack2(acc[r][0], v0, v1);
        unpack2(acc[r][1], v2, v3);
        float v[4] = { v0 + bias[0], v1 + bias[1], v2 + bias[2], v3 + bias[3] };
#pragma unroll
        for (int p = 0; p < 4; p++) {
            int col = n0 + c0 + p;
            if (col < 600) g_Gloc[(size_t)row * 600 + col] = v[p];
        }
    }
}

// =======================================================================
// Kernel B: P_t = emb_t @ W_tt ; P_s = emb_s @ W_ss
// =======================================================================
__global__ void kernB(const float* __restrict__ emb_t, const float* __restrict__ W_tt,
                      const float* __restrict__ emb_s, const float* __restrict__ W_ss)
{
    int i = blockIdx.x * blockDim.x + threadIdx.x;
    if (i >= 92 * 100 * 2) return;
    int which = i / 9200;
    int r = i % 9200;
    int s = r / 100, j = r % 100;
    const float* e = which ? emb_s : emb_t;
    const float* W = which ? W_ss : W_tt;
    float acc = 0.f;
#pragma unroll
    for (int d = 0; d < 12; d++) acc += e[s * 12 + d] * W[d * 100 + j];
    (which ? g_Ps : g_Pt)[s * 100 + j] = acc;
}

// =======================================================================
// Kernel C: gather + tsg -> scratch [t][b][ pre(400) | tsg(100) ]
// =======================================================================
__global__ void kernC(const int* __restrict__ traj,
                      const int* __restrict__ tu, const int* __restrict__ tl,
                      const int* __restrict__ tu_slot, const int* __restrict__ tl_slot,
                      const int* __restrict__ su, const int* __restrict__ sl,
                      const int* __restrict__ su_slot, const int* __restrict__ sl_slot)
{
    const int w = threadIdx.x >> 5, lane = threadIdx.x & 31;
    const int token = blockIdx.x * 8 + w;
    const int bb = token >> 8, t = token & 255;

    const int idx = traj[token];
    const float ut = (float)tu_slot[token], lt = (float)tl_slot[token];
    const float us = (float)su_slot[token], ls = (float)sl_slot[token];
    const float rdt = 1.f / fmaxf(ut + lt, 1.f);
    const float rds = 1.f / fmaxf(us + ls, 1.f);
    const float* Ptl = g_Pt + tl[token] * 100;
    const float* Ptu = g_Pt + tu[token] * 100;
    const float* Psl = g_Ps + sl[token] * 100;
    const float* Psu = g_Ps + su[token] * 100;

    const float* g = g_Gloc + (size_t)idx * 600;
    float* o = g_scr + ((size_t)t * BATCH + bb) * 500;

    const float4* g4 = (const float4*)g;
    float4* o4 = (float4*)o;
    for (int q = lane; q < 100; q += 32) o4[q] = g4[q];

    for (int j = lane; j < 100; j += 32) {
        float pt = g[400 + j] + (ut * Ptl[j] + lt * Ptu[j]) * rdt;
        float ps = g[500 + j] + (us * Psl[j] + ls * Psu[j]) * rds;
        o[400 + j] = sigf(pt) * sigf(ps);
    }
}

// =======================================================================
// Kernel D v5: column-ownership with 2-way k split. 800 threads (25 warps).
//  tid = 2*n + half : n in [0,400) output column, half selects k range.
//  h rows padded to 104 floats: half0 holds h[0..49] at [0,52),
//  half1 holds h[50..99] at [52,104); pads stay zero forever.
//  Each thread: 26 weight pairs in regs, 13 LDS.128 h loads, 26 FFMA2,
//  one shfl_xor(1) to combine halves, even lane does activation + STS.
//  Phase 2: 700 (r,j) items 1:1 on threads, c in registers.
//  Scratch staged 2 steps ahead via cp.async.bulk.
// =======================================================================
__global__ void __launch_bounds__(800, 1)
kernD(const float* __restrict__ W_hh, float* __restrict__ out)
{
    __shared__ __align__(16) float hbuf[2][ROWS_PER_CTA][HSTRIDE];
    __shared__ __align__(16) float acts[ROWS_PER_CTA][400];
    __shared__ __align__(16) float sscr[2][ROWS_PER_CTA * 500];
    __shared__ __align__(8)  ull  smbar[2];

    const int tid = threadIdx.x;
    const int n = tid >> 1, half = tid & 1;  // column n, k-half
    const int gate = n / 100;                // 0:i 1:f 2:g 3:o
    const int row0 = blockIdx.x * ROWS_PER_CTA;

    // phase-2 assignment
    const int r_2 = tid / 100, j_2 = tid % 100;
    const bool p2act = (tid < 700);

    // ---- weights: 26 (k,k+1) pairs for column n, k in [50*half, 50*half+50) ----
    ull w[26];
#pragma unroll
    for (int m = 0; m < 26; m++) {
        float lo = 0.f, hi = 0.f;
        if (m < 25) {
            int k0 = half * 50 + 2 * m;
            lo = W_hh[k0 * 400 + n];
            hi = W_hh[(k0 + 1) * 400 + n];
        }
        w[m] = pack2(lo, hi);
    }

    // ---- init smem ----
    {
        float* p = &hbuf[0][0][0];
        for (int i = tid; i < 2 * ROWS_PER_CTA * HSTRIDE; i += 800) p[i] = 0.f;
    }
    uint32_t mb0 = smem_u32(&smbar[0]);
    uint32_t mb1 = smem_u32(&smbar[1]);
    uint32_t sc0 = smem_u32(&sscr[0][0]);
    uint32_t sc1 = smem_u32(&sscr[1][0]);
    if (tid == 0) { mbar_init(mb0, 1); mbar_init(mb1, 1); }
    __syncthreads();

    const float* scr_base = g_scr + (size_t)row0 * 500;
    if (tid == 0) {
        mbar_expect_tx(mb0, SCR_BYTES);
        bulk_g2s(sc0, scr_base, SCR_BYTES, mb0);
        mbar_expect_tx(mb1, SCR_BYTES);
        bulk_g2s(sc1, scr_base + (size_t)BATCH * 500, SCR_BYTES, mb1);
    }

    float creg = 0.f;                        // cell state for phase-2 item

#pragma unroll 1
    for (int t = 0; t < TSTEPS; t++) {
        const int buf = t & 1;
        mbar_wait(buf ? mb1 : mb0, (t >> 1) & 1);

        const float* sb = sscr[buf];
        const float* hc = &hbuf[buf][0][0];
        float* hn = &hbuf[buf ^ 1][0][0];

        // ---------------- phase 1: gate pre-sums + activations ----------------
#pragma unroll
        for (int r = 0; r < ROWS_PER_CTA; r++) {
            const ulonglong2* h2 = (const ulonglong2*)(hc + r * HSTRIDE + half * 52);
            ull a0 = 0ull, a1 = 0ull;
#pragma unroll
            for (int m = 0; m < 13; m++) {
                ulonglong2 hv = h2[m];
                fma2(a0, hv.x, w[2 * m]);
                fma2(a1, hv.y, w[2 * m + 1]);
            }
            float xl, xh, s0, s1;
            unpack2(a0, xl, xh); s0 = xl + xh;
            unpack2(a1, xl, xh); s1 = xl + xh;
            float part = s0 + s1;
            part += __shfl_xor_sync(0xffffffffu, part, 1);
            if (half == 0) {
                float v = part + sb[r * 500 + n];
                acts[r][n] = (gate == 2) ? tanh_fast(v) : sigf(v);
            }
        }
        __syncthreads();

        // ---------------- phase 2: c/h update ----------------
        if (p2act) {
            const float* ap = &acts[r_2][0];
            float gi = ap[j_2], gf = ap[100 + j_2], gg = ap[200 + j_2], go = ap[300 + j_2];
            float tsg = sb[r_2 * 500 + 400 + j_2];
            float cN = gf * creg + gi * tsg * gg;
            creg = cN;
            float h = go * tanh_fast(cN);
            hn[r_2 * HSTRIDE + j_2 + (j_2 >= 50 ? 2 : 0)] = h;
            if (t == TSTEPS - 1 && row0 + r_2 < BATCH) out[(row0 + r_2) * 100 + j_2] = h;
        }
        __syncthreads();

        if (t + 2 < TSTEPS && tid == 0) {
            uint32_t mb = buf ? mb1 : mb0;
            mbar_expect_tx(mb, SCR_BYTES);
            bulk_g2s(buf ? sc1 : sc0, scr_base + (size_t)(t + 2) * BATCH * 500, SCR_BYTES, mb);
        }
    }
}

// =======================================================================
// launch
// =======================================================================
extern "C" void kernel_launch(void* const* d_in, const int* in_sizes, int n_in,
                              void* d_out, int out_size)
{
    (void)in_sizes; (void)n_in; (void)out_size;
    const int*   traj    = (const int*)d_in[0];
    const int*   tu      = (const int*)d_in[3];
    const int*   tl      = (const int*)d_in[4];
    const int*   tu_s    = (const int*)d_in[5];
    const int*   tl_s    = (const int*)d_in[6];
    const int*   su      = (const int*)d_in[7];
    const int*   sl      = (const int*)d_in[8];
    const int*   su_s    = (const int*)d_in[9];
    const int*   sl_s    = (const int*)d_in[10];
    const float* emb_loc = (const float*)d_in[11];
    const float* emb_t   = (const float*)d_in[12];
    const float* emb_s   = (const float*)d_in[13];
    const float* W_ih    = (const float*)d_in[14];
    const float* W_hh    = (const float*)d_in[15];
    const float* b       = (const float*)d_in[16];
    const float* W_xt    = (const float*)d_in[17];
    const float* W_tt    = (const float*)d_in[18];
    const float* b_t     = (const float*)d_in[19];
    const float* W_xs    = (const float*)d_in[20];
    const float* W_ss    = (const float*)d_in[21];
    const float* b_s     = (const float*)d_in[22];
    float* out = (float*)d_out;

    dim3 gA((LOCN + 63) / 64, 10);
    kernA<<<gA, 256>>>(emb_loc, W_ih, W_xt, W_xs, b, b_t, b_s);

    kernB<<<(92 * 100 * 2 + 255) / 256, 256>>>(emb_t, W_tt, emb_s, W_ss);

    kernC<<<(BATCH * TSTEPS) / 8, 256>>>(traj, tu, tl, tu_s, tl_s, su, sl, su_s, sl_s);

    kernD<<<NCTA, 800>>>(W_hh, out);
}

// round 6
// speedup vs baseline: 1.3125x; 1.0608x over previous
#include <cuda_runtime.h>
#include <cstdint>

typedef unsigned long long ull;

#define LOCN   40001
#define BATCH  1024
#define TSTEPS 256

#define ROWS_PER_CTA 7
#define NCTA ((BATCH + ROWS_PER_CTA - 1) / ROWS_PER_CTA)   // 147
#define HSTRIDE 112                          // 4 quarters of 28 floats; real k=25q+i at 28q+i
#define SCR_BYTES (ROWS_PER_CTA * 500 * 4)   // 14000, multiple of 16

// ---------------- device scratch ----------------
__device__ float g_Gloc[(size_t)LOCN * 600];
__device__ float g_Pt[92 * 100];
__device__ float g_Ps[92 * 100];
__device__ float g_scr[(size_t)TSTEPS * BATCH * 500 + 4096];

// ---------------- helpers ----------------
__device__ __forceinline__ float sigf(float x) { return 1.f / (1.f + __expf(-x)); }
__device__ __forceinline__ float tanh_fast(float x) { return 1.f - 2.f / (1.f + __expf(2.f * x)); }

__device__ __forceinline__ ull pack2(float lo, float hi) {
    ull r; asm("mov.b64 %0, {%1, %2};" : "=l"(r) : "f"(lo), "f"(hi)); return r;
}
__device__ __forceinline__ void unpack2(ull v, float& lo, float& hi) {
    asm("mov.b64 {%0, %1}, %2;" : "=f"(lo), "=f"(hi) : "l"(v));
}
__device__ __forceinline__ void fma2(ull& acc, ull a, ull b) {
    asm("fma.rn.f32x2 %0, %1, %2, %0;" : "+l"(acc) : "l"(a), "l"(b));
}
__device__ __forceinline__ uint32_t smem_u32(const void* p) {
    uint32_t a;
    asm("{ .reg .u64 t; cvta.to.shared.u64 t, %1; cvt.u32.u64 %0, t; }" : "=r"(a) : "l"(p));
    return a;
}
__device__ __forceinline__ void mbar_init(uint32_t mbar, uint32_t cnt) {
    asm volatile("mbarrier.init.shared.b64 [%0], %1;" :: "r"(mbar), "r"(cnt) : "memory");
}
__device__ __forceinline__ void mbar_expect_tx(uint32_t mbar, uint32_t bytes) {
    asm volatile("mbarrier.arrive.expect_tx.shared.b64 _, [%0], %1;" :: "r"(mbar), "r"(bytes) : "memory");
}
__device__ __forceinline__ void bulk_g2s(uint32_t dst, const void* src, uint32_t bytes, uint32_t mbar) {
    asm volatile("cp.async.bulk.shared::cta.global.mbarrier::complete_tx::bytes [%0], [%1], %2, [%3];"
                 :: "r"(dst), "l"(src), "r"(bytes), "r"(mbar) : "memory");
}
__device__ __forceinline__ void mbar_wait(uint32_t mbar, uint32_t parity) {
    uint32_t done;
    asm volatile("{\n\t.reg .pred p;\n\t"
                 "mbarrier.try_wait.parity.acquire.cta.shared::cta.b64 p, [%1], %2;\n\t"
                 "selp.b32 %0, 1, 0, p;\n\t}"
                 : "=r"(done) : "r"(mbar), "r"(parity) : "memory");
    if (!done) {
        asm volatile("{\n\t.reg .pred P1;\n\t"
                     "WL_%=:\n\t"
                     "mbarrier.try_wait.parity.acquire.cta.shared::cta.b64 P1, [%0], %1, 0x989680;\n\t"
                     "@P1 bra.uni WD_%=;\n\t"
                     "bra.uni WL_%=;\n\t"
                     "WD_%=:\n\t}"
                     :: "r"(mbar), "r"(parity) : "memory");
    }
}

// =======================================================================
// Kernel A: Gloc = emb_loc @ [W_ih|W_xt|W_xs] + biases
// =======================================================================
__global__ void kernA(const float* __restrict__ emb_loc,
                      const float* __restrict__ W_ih,
                      const float* __restrict__ W_xt,
                      const float* __restrict__ W_xs,
                      const float* __restrict__ b,
                      const float* __restrict__ b_t,
                      const float* __restrict__ b_s)
{
    __shared__ __align__(16) float As[50 * 64];
    __shared__ __align__(16) float Bs[50 * 64];

    const int tid = threadIdx.x;
    const int m0 = blockIdx.x * 64;
    const int n0 = blockIdx.y * 64;
    const int tx = tid & 15, ty = tid >> 4;
    const int r0 = ty * 4, c0 = tx * 4;

    ull acc[4][2];
#pragma unroll
    for (int i = 0; i < 4; i++) { acc[i][0] = 0ull; acc[i][1] = 0ull; }

    for (int kp = 0; kp < 100; kp += 50) {
        for (int i = tid; i < 64 * 50; i += 256) {
            int r = i / 50, k = i % 50;
            int row = m0 + r;
            As[k * 64 + r] = (row < LOCN) ? emb_loc[(size_t)row * 100 + kp + k] : 0.f;
        }
        for (int i = tid; i < 64 * 50; i += 256) {
            int k = i / 64, c = i % 64;
            int col = n0 + c, kk = kp + k;
            float v = 0.f;
            if (col < 400)      v = W_ih[kk * 400 + col];
            else if (col < 500) v = W_xt[kk * 100 + (col - 400)];
            else if (col < 600) v = W_xs[kk * 100 + (col - 500)];
            Bs[k * 64 + c] = v;
        }
        __syncthreads();

#pragma unroll 5
        for (int k = 0; k < 50; k++) {
            float4 a4 = *(const float4*)(As + k * 64 + r0);
            ulonglong2 bv = *(const ulonglong2*)(Bs + k * 64 + c0);
            ull a0 = pack2(a4.x, a4.x);
            ull a1 = pack2(a4.y, a4.y);
            ull a2 = pack2(a4.z, a4.z);
            ull a3 = pack2(a4.w, a4.w);
            fma2(acc[0][0], a0, bv.x); fma2(acc[0][1], a0, bv.y);
            fma2(acc[1][0], a1, bv.x); fma2(acc[1][1], a1, bv.y);
            fma2(acc[2][0], a2, bv.x); fma2(acc[2][1], a2, bv.y);
            fma2(acc[3][0], a3, bv.x); fma2(acc[3][1], a3, bv.y);
        }
        __syncthreads();
    }

    float bias[4];
#pragma unroll
    for (int p = 0; p < 4; p++) {
        int col = n0 + c0 + p;
        float bv = 0.f;
        if (col < 400)      bv = b[col];
        else if (col < 500) bv = b_t[col - 400];
        else if (col < 600) bv = b_s[col - 500];
        bias[p] = bv;
    }
#pragma unroll
    for (int r = 0; r < 4; r++) {
        int row = m0 + r0 + r;
        if (row >= LOCN) continue;
        float v0, v1, v2, v3;
        unpack2(acc[r][0], v0, v1);
        unpack2(acc[r][1], v2, v3);
        float v[4] = { v0 + bias[0], v1 + bias[1], v2 + bias[2], v3 + bias[3] };
#pragma unroll
        for (int p = 0; p < 4; p++) {
            int col = n0 + c0 + p;
            if (col < 600) g_Gloc[(size_t)row * 600 + col] = v[p];
        }
    }
}

// =======================================================================
// Kernel B: P_t = emb_t @ W_tt ; P_s = emb_s @ W_ss
// =======================================================================
__global__ void kernB(const float* __restrict__ emb_t, const float* __restrict__ W_tt,
                      const float* __restrict__ emb_s, const float* __restrict__ W_ss)
{
    int i = blockIdx.x * blockDim.x + threadIdx.x;
    if (i >= 92 * 100 * 2) return;
    int which = i / 9200;
    int r = i % 9200;
    int s = r / 100, j = r % 100;
    const float* e = which ? emb_s : emb_t;
    const float* W = which ? W_ss : W_tt;
    float acc = 0.f;
#pragma unroll
    for (int d = 0; d < 12; d++) acc += e[s * 12 + d] * W[d * 100 + j];
    (which ? g_Ps : g_Pt)[s * 100 + j] = acc;
}

// =======================================================================
// Kernel C: gather + tsg -> scratch [t][b][ pre(400) | tsg(100) ]
// =======================================================================
__global__ void kernC(const int* __restrict__ traj,
                      const int* __restrict__ tu, const int* __restrict__ tl,
                      const int* __restrict__ tu_slot, const int* __restrict__ tl_slot,
                      const int* __restrict__ su, const int* __restrict__ sl,
                      const int* __restrict__ su_slot, const int* __restrict__ sl_slot)
{
    const int w = threadIdx.x >> 5, lane = threadIdx.x & 31;
    const int token = blockIdx.x * 8 + w;
    const int bb = token >> 8, t = token & 255;

    const int idx = traj[token];
    const float ut = (float)tu_slot[token], lt = (float)tl_slot[token];
    const float us = (float)su_slot[token], ls = (float)sl_slot[token];
    const float rdt = 1.f / fmaxf(ut + lt, 1.f);
    const float rds = 1.f / fmaxf(us + ls, 1.f);
    const float* Ptl = g_Pt + tl[token] * 100;
    const float* Ptu = g_Pt + tu[token] * 100;
    const float* Psl = g_Ps + sl[token] * 100;
    const float* Psu = g_Ps + su[token] * 100;

    const float* g = g_Gloc + (size_t)idx * 600;
    float* o = g_scr + ((size_t)t * BATCH + bb) * 500;

    const float4* g4 = (const float4*)g;
    float4* o4 = (float4*)o;
    for (int q = lane; q < 100; q += 32) o4[q] = g4[q];

    for (int j = lane; j < 100; j += 32) {
        float pt = g[400 + j] + (ut * Ptl[j] + lt * Ptu[j]) * rdt;
        float ps = g[500 + j] + (us * Psl[j] + ls * Psu[j]) * rds;
        o[400 + j] = sigf(pt) * sigf(ps);
    }
}

// =======================================================================
// Kernel D v6: column-PAIR ownership + 4-way k split. 800 threads.
//  tid = p*4 + q : p in [0,200) owns columns {p, p+200}; q = k-quarter.
//  h padded to 112: real k = 25*qq + i stored at 28*qq + i (pads stay 0).
//  Per thread-row: 7 LDS.128 -> 28 FFMA2 (2 cols x 14 pairs), 2-shfl
//  reduce-scatter over q lanes, branch-free activation on lanes q=0 / q=2,
//  STS into acts. Phase 2: 700 (r,j) items, c in regs.
//  Scratch staged 2 steps ahead via cp.async.bulk.
// =======================================================================
__global__ void __launch_bounds__(800, 1)
kernD(const float* __restrict__ W_hh, float* __restrict__ out)
{
    __shared__ __align__(16) float hbuf[2][ROWS_PER_CTA][HSTRIDE];
    __shared__ __align__(16) float acts[ROWS_PER_CTA][400];
    __shared__ __align__(16) float sscr[2][ROWS_PER_CTA * 500];
    __shared__ __align__(8)  ull  smbar[2];

    const int tid = threadIdx.x;
    const int p = tid >> 2, q = tid & 3;     // column pair {p, p+200}, k-quarter
    const int row0 = blockIdx.x * ROWS_PER_CTA;

    // this lane's output column after reduce-scatter (lanes q<2 -> p, q>=2 -> p+200)
    const int mycol = p + ((q & 2) ? 200 : 0);
    const int mygate = mycol / 100;          // 0:i 1:f 2:g 3:o
    // branch-free activation params: sig: s=sig(v), act=s ; tanh: s=sig(2v), act=2s-1
    const float ascale = (mygate == 2) ? 2.f : 1.f;
    const float aA     = (mygate == 2) ? 2.f : 1.f;
    const float aB     = (mygate == 2) ? -1.f : 0.f;
    const bool doST = ((q & 1) == 0);        // lanes 0 and 2 store

    // phase-2 assignment (loop-invariant)
    const int r_2 = tid / 100, j_2 = tid % 100;
    const bool p2act = (tid < 700);
    const int hslot_2 = 28 * (j_2 / 25) + (j_2 % 25);   // padded h offset for j_2
    const bool p2out = (row0 + r_2 < BATCH);

    // ---- weights: 14 (k,k+1) pairs per column, k-range = quarter q ----
    // pair m covers padded offsets {28q+2m, 28q+2m+1} -> real k = 25q+2m, 25q+2m+1
    ull wA[14], wB[14];
#pragma unroll
    for (int m = 0; m < 14; m++) {
        int i0 = 2 * m, i1 = 2 * m + 1;
        float a0 = 0.f, a1 = 0.f, b0 = 0.f, b1 = 0.f;
        if (i0 < 25) {
            int k = 25 * q + i0;
            a0 = W_hh[k * 400 + p];
            b0 = W_hh[k * 400 + p + 200];
        }
        if (i1 < 25) {
            int k = 25 * q + i1;
            a1 = W_hh[k * 400 + p];
            b1 = W_hh[k * 400 + p + 200];
        }
        wA[m] = pack2(a0, a1);
        wB[m] = pack2(b0, b1);
    }

    // ---- init smem ----
    {
        float* pp = &hbuf[0][0][0];
        for (int i = tid; i < 2 * ROWS_PER_CTA * HSTRIDE; i += 800) pp[i] = 0.f;
    }
    uint32_t mb0 = smem_u32(&smbar[0]);
    uint32_t mb1 = smem_u32(&smbar[1]);
    uint32_t sc0 = smem_u32(&sscr[0][0]);
    uint32_t sc1 = smem_u32(&sscr[1][0]);
    if (tid == 0) { mbar_init(mb0, 1); mbar_init(mb1, 1); }
    __syncthreads();

    const float* scr_base = g_scr + (size_t)row0 * 500;
    if (tid == 0) {
        mbar_expect_tx(mb0, SCR_BYTES);
        bulk_g2s(sc0, scr_base, SCR_BYTES, mb0);
        mbar_expect_tx(mb1, SCR_BYTES);
        bulk_g2s(sc1, scr_base + (size_t)BATCH * 500, SCR_BYTES, mb1);
    }

    float creg = 0.f;                        // cell state for phase-2 item

#pragma unroll 1
    for (int t = 0; t < TSTEPS; t++) {
        const int buf = t & 1;
        mbar_wait(buf ? mb1 : mb0, (t >> 1) & 1);

        const float* sb = sscr[buf];
        const float* hc = &hbuf[buf][0][0];
        float* hn = &hbuf[buf ^ 1][0][0];

        // ---------------- phase 1: gate pre-sums + activations ----------------
#pragma unroll
        for (int r = 0; r < ROWS_PER_CTA; r++) {
            const ulonglong2* h2 = (const ulonglong2*)(hc + r * HSTRIDE + q * 28);
            ull aaA = 0ull, aaB = 0ull;
#pragma unroll
            for (int m = 0; m < 7; m++) {
                ulonglong2 hv = h2[m];
                fma2(aaA, hv.x, wA[2 * m]);
                fma2(aaB, hv.x, wB[2 * m]);
                fma2(aaA, hv.y, wA[2 * m + 1]);
                fma2(aaB, hv.y, wB[2 * m + 1]);
            }
            float xl, xh, sA, sB;
            unpack2(aaA, xl, xh); sA = xl + xh;
            unpack2(aaB, xl, xh); sB = xl + xh;

            // reduce-scatter over the 4 q-lanes
            float tsend = (q & 2) ? sA : sB;
            float trecv = __shfl_xor_sync(0xffffffffu, tsend, 2);
            float v = ((q & 2) ? sB : sA) + trecv;
            v += __shfl_xor_sync(0xffffffffu, v, 1);
            // lanes q in {0,1}: full sum col p ; q in {2,3}: full sum col p+200

            v += sb[r * 500 + mycol];
            float s = 1.f / (1.f + __expf(-ascale * v));
            float act = fmaf(s, aA, aB);
            if (doST) acts[r][mycol] = act;
        }
        __syncthreads();

        // ---------------- phase 2: c/h update ----------------
        if (p2act) {
            const float* ap = &acts[r_2][0];
            float gi = ap[j_2], gf = ap[100 + j_2], gg = ap[200 + j_2], go = ap[300 + j_2];
            float tsg = sb[r_2 * 500 + 400 + j_2];
            float cN = gf * creg + gi * tsg * gg;
            creg = cN;
            float h = go * tanh_fast(cN);
            hn[r_2 * HSTRIDE + hslot_2] = h;
            if (t == TSTEPS - 1 && p2out) out[(row0 + r_2) * 100 + j_2] = h;
        }
        __syncthreads();

        if (t + 2 < TSTEPS && tid == 0) {
            uint32_t mb = buf ? mb1 : mb0;
            mbar_expect_tx(mb, SCR_BYTES);
            bulk_g2s(buf ? sc1 : sc0, scr_base + (size_t)(t + 2) * BATCH * 500, SCR_BYTES, mb);
        }
    }
}

// =======================================================================
// launch
// =======================================================================
extern "C" void kernel_launch(void* const* d_in, const int* in_sizes, int n_in,
                              void* d_out, int out_size)
{
    (void)in_sizes; (void)n_in; (void)out_size;
    const int*   traj    = (const int*)d_in[0];
    const int*   tu      = (const int*)d_in[3];
    const int*   tl      = (const int*)d_in[4];
    const int*   tu_s    = (const int*)d_in[5];
    const int*   tl_s    = (const int*)d_in[6];
    const int*   su      = (const int*)d_in[7];
    const int*   sl      = (const int*)d_in[8];
    const int*   su_s    = (const int*)d_in[9];
    const int*   sl_s    = (const int*)d_in[10];
    const float* emb_loc = (const float*)d_in[11];
    const float* emb_t   = (const float*)d_in[12];
    const float* emb_s   = (const float*)d_in[13];
    const float* W_ih    = (const float*)d_in[14];
    const float* W_hh    = (const float*)d_in[15];
    const float* b       = (const float*)d_in[16];
    const float* W_xt    = (const float*)d_in[17];
    const float* W_tt    = (const float*)d_in[18];
    const float* b_t     = (const float*)d_in[19];
    const float* W_xs    = (const float*)d_in[20];
    const float* W_ss    = (const float*)d_in[21];
    const float* b_s     = (const float*)d_in[22];
    float* out = (float*)d_out;

    dim3 gA((LOCN + 63) / 64, 10);
    kernA<<<gA, 256>>>(emb_loc, W_ih, W_xt, W_xs, b, b_t, b_s);

    kernB<<<(92 * 100 * 2 + 255) / 256, 256>>>(emb_t, W_tt, emb_s, W_ss);

    kernC<<<(BATCH * TSTEPS) / 8, 256>>>(traj, tu, tl, tu_s, tl_s, su, sl, su_s, sl_s);

    kernD<<<NCTA, 800>>>(W_hh, out);
}